// round 1
// baseline (speedup 1.0000x reference)
#include <cuda_runtime.h>
#include <math.h>

// Problem constants
#define BB   32
#define TT   120
#define JJ   24
#define EE   128
#define HH   8
#define DH   16
#define DDIM 3072
#define FFD  256
#define NTOK (BB*TT)          // 3840
#define NEL  (NTOK*DDIM)      // 11,796,480
#define NROWCH 30             // NTOK/128 row chunks for BN stats

// ---------------- scratch (static device globals; no allocation) ----------------
__device__ float g_bufA[NEL];
__device__ float g_bufB[NEL];
__device__ float g_bufC[NEL];
__device__ float g_bufD[NEL];
__device__ float g_res1[NEL];
__device__ float g_res2[NEL];
__device__ float g_h1[NTOK*FFD];
__device__ float g_wqt[HH*JJ*DH*EE];
__device__ float g_wkt[HH*JJ*DH*EE];
__device__ float g_wvt[HH*JJ*DH*EE];
__device__ float g_wqs[HH*JJ*DH*EE];
__device__ float g_ps [NROWCH*DDIM];
__device__ float g_ps2[NROWCH*DDIM];
__device__ float g_mean[3*DDIM];
__device__ float g_var [3*DDIM];

// ---------------- weight repack: (H,J,d,E) -> (J, H*d, E) ----------------
__global__ void repack_w(const float* __restrict__ in, float* __restrict__ out) {
    int idx = blockIdx.x * 256 + threadIdx.x;   // total H*J*d*E = 393216
    if (idx >= HH*JJ*DH*EE) return;
    int e  = idx & (EE-1);
    int r  = idx >> 7;        // ((h*J + j)*d + dd)
    int dd = r & (DH-1);
    int hj = r >> 4;
    int j  = hj % JJ;
    int h  = hj / JJ;
    out[(j*(HH*DH) + h*DH + dd)*EE + e] = in[idx];
}

// ---------------- generic SGEMM: C = A(MxK) * B^T(NxK) [+bias][+res][relu] ----------------
// Block tile 128x128, BK=16, 256 threads, 8x8 per thread.
// grid.x = N/128 tiles, grid.y = M/128 tiles, grid.z = batch.
#define BM 128
#define BN 128
#define BK 16
__global__ __launch_bounds__(256) void sgemm(
    const float* __restrict__ A, long lda, long sA,
    const float* __restrict__ B, long ldb, long sB,
    float* __restrict__ C, long ldc, long sC,
    const float* __restrict__ bias,
    const float* __restrict__ res, long ldres,
    int K, int relu)
{
    __shared__ float As[BK][BM];
    __shared__ float Bs[BK][BN];
    const float* Ab = A + (long)blockIdx.z*sA + (long)blockIdx.y*BM*lda;
    const float* Bb = B + (long)blockIdx.z*sB + (long)blockIdx.x*BN*ldb;
    int tid = threadIdx.x;
    int tr = (tid >> 4) * 8;
    int tc = (tid & 15) * 8;
    float acc[8][8];
    #pragma unroll
    for (int i = 0; i < 8; i++)
        #pragma unroll
        for (int j = 0; j < 8; j++) acc[i][j] = 0.f;

    for (int k0 = 0; k0 < K; k0 += BK) {
        #pragma unroll
        for (int i = 0; i < 2; i++) {
            int s   = tid*2 + i;            // 0..511 float4 slots
            int row = s >> 2;
            int kq  = (s & 3) * 4;
            float4 a = *(const float4*)(Ab + (long)row*lda + k0 + kq);
            As[kq+0][row]=a.x; As[kq+1][row]=a.y; As[kq+2][row]=a.z; As[kq+3][row]=a.w;
            float4 b = *(const float4*)(Bb + (long)row*ldb + k0 + kq);
            Bs[kq+0][row]=b.x; Bs[kq+1][row]=b.y; Bs[kq+2][row]=b.z; Bs[kq+3][row]=b.w;
        }
        __syncthreads();
        #pragma unroll
        for (int kk = 0; kk < BK; kk++) {
            float a[8], b[8];
            *(float4*)(a)   = *(const float4*)&As[kk][tr];
            *(float4*)(a+4) = *(const float4*)&As[kk][tr+4];
            *(float4*)(b)   = *(const float4*)&Bs[kk][tc];
            *(float4*)(b+4) = *(const float4*)&Bs[kk][tc+4];
            #pragma unroll
            for (int i = 0; i < 8; i++)
                #pragma unroll
                for (int j = 0; j < 8; j++)
                    acc[i][j] = fmaf(a[i], b[j], acc[i][j]);
        }
        __syncthreads();
    }

    float* Cb = C + (long)blockIdx.z*sC;
    #pragma unroll
    for (int i = 0; i < 8; i++) {
        long m = (long)blockIdx.y*BM + tr + i;
        #pragma unroll
        for (int j = 0; j < 8; j++) {
            long n = (long)blockIdx.x*BN + tc + j;
            float v = acc[i][j];
            if (bias) v += bias[n];
            if (res)  v += res[m*ldres + n];
            if (relu) v = fmaxf(v, 0.f);
            Cb[m*ldc + n] = v;
        }
    }
}

// ---------------- temporal attention: one block per (j,h,b); causal over T ----------------
// q/k/v layout: [(b*T+t)*J + j]*128 + h*16 + dd
// out (concat) layout: [(b*T+t)*3072 + h*384 + j*16 + dd]
__global__ __launch_bounds__(128) void temporal_attn(
    const float* __restrict__ q, const float* __restrict__ k,
    const float* __restrict__ v, float* __restrict__ out)
{
    int j = blockIdx.x, h = blockIdx.y, b = blockIdx.z;
    __shared__ float Ks[TT][DH];
    __shared__ float Vs[TT][DH];
    int tid = threadIdx.x;
    for (int idx = tid; idx < TT*DH; idx += 128) {
        int t = idx >> 4, dd = idx & 15;
        long off = ((long)(b*TT + t)*JJ + j)*128 + h*DH + dd;
        Ks[t][dd] = k[off];
        Vs[t][dd] = v[off];
    }
    __syncthreads();
    int t = tid;
    if (t < TT) {
        float qr[DH];
        long qoff = ((long)(b*TT + t)*JJ + j)*128 + h*DH;
        #pragma unroll
        for (int dd = 0; dd < DH; dd++) qr[dd] = q[qoff + dd];
        float m = -1e30f, l = 0.f, acc[DH];
        #pragma unroll
        for (int dd = 0; dd < DH; dd++) acc[dd] = 0.f;
        for (int s = 0; s <= t; s++) {
            float sc = 0.f;
            #pragma unroll
            for (int dd = 0; dd < DH; dd++) sc = fmaf(qr[dd], Ks[s][dd], sc);
            sc *= 0.25f;
            float mn = fmaxf(m, sc);
            float corr = __expf(m - mn);
            float p    = __expf(sc - mn);
            l = l*corr + p;
            #pragma unroll
            for (int dd = 0; dd < DH; dd++) acc[dd] = fmaf(acc[dd], corr, p*Vs[s][dd]);
            m = mn;
        }
        float inv = 1.f / l;
        long ooff = (long)(b*TT + t)*DDIM + h*(JJ*DH) + j*DH;
        #pragma unroll
        for (int dd = 0; dd < DH; dd++) out[ooff + dd] = acc[dd]*inv;
    }
}

// ---------------- spatial attention: one block per token, one warp per head ----------------
__global__ __launch_bounds__(256) void spatial_attn(
    const float* __restrict__ q, const float* __restrict__ k,
    const float* __restrict__ v, float* __restrict__ out)
{
    int tok  = blockIdx.x;
    int h    = threadIdx.x >> 5;
    int lane = threadIdx.x & 31;
    __shared__ float Ks[HH][JJ][DH];
    __shared__ float Vs[HH][JJ][DH];
    for (int idx = lane; idx < JJ*DH; idx += 32) {
        int jj = idx >> 4, dd = idx & 15;
        long off = ((long)tok*JJ + jj)*128 + h*DH + dd;
        Ks[h][jj][dd] = k[off];
        Vs[h][jj][dd] = v[off];
    }
    __syncwarp();
    if (lane < JJ) {
        int j = lane;
        float qr[DH];
        long qoff = ((long)tok*JJ + j)*128 + h*DH;
        #pragma unroll
        for (int dd = 0; dd < DH; dd++) qr[dd] = q[qoff + dd];
        float s[JJ];
        float m = -1e30f;
        #pragma unroll
        for (int kk = 0; kk < JJ; kk++) {
            float sc = 0.f;
            #pragma unroll
            for (int dd = 0; dd < DH; dd++) sc = fmaf(qr[dd], Ks[h][kk][dd], sc);
            sc *= 0.25f;
            s[kk] = sc;
            m = fmaxf(m, sc);
        }
        float l = 0.f;
        #pragma unroll
        for (int kk = 0; kk < JJ; kk++) { s[kk] = __expf(s[kk] - m); l += s[kk]; }
        float acc[DH];
        #pragma unroll
        for (int dd = 0; dd < DH; dd++) acc[dd] = 0.f;
        #pragma unroll
        for (int kk = 0; kk < JJ; kk++)
            #pragma unroll
            for (int dd = 0; dd < DH; dd++) acc[dd] = fmaf(s[kk], Vs[h][kk][dd], acc[dd]);
        float inv = 1.f / l;
        long ooff = (long)tok*DDIM + h*(JJ*DH) + j*DH;
        #pragma unroll
        for (int dd = 0; dd < DH; dd++) out[ooff + dd] = acc[dd]*inv;
    }
}

// ---------------- BN stats (deterministic two-stage) ----------------
// stage1: grid (DDIM/256, NROWCH); each block: 128 rows x 256 channels partial sums
__global__ __launch_bounds__(256) void bn_stats1(
    const float* __restrict__ in, float* __restrict__ ps, float* __restrict__ ps2)
{
    int c = blockIdx.x*256 + threadIdx.x;
    const float* p = in + (long)blockIdx.y*128*DDIM + c;
    float s = 0.f, s2 = 0.f;
    #pragma unroll 4
    for (int r = 0; r < 128; r++) {
        float x = p[(long)r*DDIM];
        s  += x;
        s2 = fmaf(x, x, s2);
    }
    ps [blockIdx.y*DDIM + c] = s;
    ps2[blockIdx.y*DDIM + c] = s2;
}
// stage2: grid DDIM/256
__global__ __launch_bounds__(256) void bn_stats2(
    const float* __restrict__ ps, const float* __restrict__ ps2,
    float* __restrict__ mean, float* __restrict__ var)
{
    int c = blockIdx.x*256 + threadIdx.x;
    float s = 0.f, s2 = 0.f;
    #pragma unroll
    for (int r = 0; r < NROWCH; r++) { s += ps[r*DDIM + c]; s2 += ps2[r*DDIM + c]; }
    float m = s / (float)NTOK;
    mean[c] = m;
    var[c]  = s2 / (float)NTOK - m*m;
}

// ---------------- elementwise: att = bn_t(res1) + bn_s(res2) ----------------
__global__ __launch_bounds__(256) void combine_att(
    const float* __restrict__ x1, const float* __restrict__ x2,
    const float* __restrict__ gt, const float* __restrict__ bt,
    const float* __restrict__ gs, const float* __restrict__ bs,
    const float* __restrict__ mean, const float* __restrict__ var,
    float* __restrict__ out)
{
    long i = (long)blockIdx.x*256 + threadIdx.x;
    if (i >= NEL) return;
    int c = (int)(i % DDIM);
    float a = (x1[i] - mean[c])        * rsqrtf(var[c]        + 1e-5f) * gt[c] + bt[c];
    float b = (x2[i] - mean[DDIM + c]) * rsqrtf(var[DDIM + c] + 1e-5f) * gs[c] + bs[c];
    out[i] = a + b;
}

// ---------------- elementwise: out = bn_f(x) ----------------
__global__ __launch_bounds__(256) void final_bn(
    const float* __restrict__ x,
    const float* __restrict__ gf, const float* __restrict__ bf,
    const float* __restrict__ mean, const float* __restrict__ var,
    float* __restrict__ out)
{
    long i = (long)blockIdx.x*256 + threadIdx.x;
    if (i >= NEL) return;
    int c = (int)(i % DDIM);
    out[i] = (x[i] - mean[c]) * rsqrtf(var[c] + 1e-5f) * gf[c] + bf[c];
}

// ---------------- launch ----------------
extern "C" void kernel_launch(void* const* d_in, const int* in_sizes, int n_in,
                              void* d_out, int out_size)
{
    const float* src  = (const float*)d_in[0];
    const float* Wq_t = (const float*)d_in[1];
    const float* Wk_t = (const float*)d_in[2];
    const float* Wv_t = (const float*)d_in[3];
    const float* Wp_t = (const float*)d_in[4];
    const float* bp_t = (const float*)d_in[5];
    const float* g_t  = (const float*)d_in[6];
    const float* b_t  = (const float*)d_in[7];
    const float* Wq_s = (const float*)d_in[8];
    const float* Wk_s = (const float*)d_in[9];
    const float* Wv_s = (const float*)d_in[10];
    const float* Wp_s = (const float*)d_in[11];
    const float* bp_s = (const float*)d_in[12];
    const float* g_s  = (const float*)d_in[13];
    const float* b_s  = (const float*)d_in[14];
    const float* W1   = (const float*)d_in[15];
    const float* b1   = (const float*)d_in[16];
    const float* W2   = (const float*)d_in[17];
    const float* b2   = (const float*)d_in[18];
    const float* g_f  = (const float*)d_in[19];
    const float* b_f  = (const float*)d_in[20];
    float* out = (float*)d_out;

    float *bufA,*bufB,*bufC,*bufD,*res1,*res2,*h1,*wqt,*wkt,*wvt,*wqs,*ps,*ps2,*mean,*var;
    cudaGetSymbolAddress((void**)&bufA, g_bufA);
    cudaGetSymbolAddress((void**)&bufB, g_bufB);
    cudaGetSymbolAddress((void**)&bufC, g_bufC);
    cudaGetSymbolAddress((void**)&bufD, g_bufD);
    cudaGetSymbolAddress((void**)&res1, g_res1);
    cudaGetSymbolAddress((void**)&res2, g_res2);
    cudaGetSymbolAddress((void**)&h1,   g_h1);
    cudaGetSymbolAddress((void**)&wqt,  g_wqt);
    cudaGetSymbolAddress((void**)&wkt,  g_wkt);
    cudaGetSymbolAddress((void**)&wvt,  g_wvt);
    cudaGetSymbolAddress((void**)&wqs,  g_wqs);
    cudaGetSymbolAddress((void**)&ps,   g_ps);
    cudaGetSymbolAddress((void**)&ps2,  g_ps2);
    cudaGetSymbolAddress((void**)&mean, g_mean);
    cudaGetSymbolAddress((void**)&var,  g_var);

    const int REPACK_BLOCKS = (HH*JJ*DH*EE + 255)/256;

    // ---- repack per-joint weights to (J, H*d, E) ----
    repack_w<<<REPACK_BLOCKS, 256>>>(Wq_t, wqt);
    repack_w<<<REPACK_BLOCKS, 256>>>(Wk_t, wkt);
    repack_w<<<REPACK_BLOCKS, 256>>>(Wv_t, wvt);
    repack_w<<<REPACK_BLOCKS, 256>>>(Wq_s, wqs);

    // ---- temporal QKV: batched over joints (z=24), M=3840, N=128, K=128 ----
    sgemm<<<dim3(1,NTOK/128,JJ),256>>>(src,DDIM,EE, wqt,EE,(long)128*128, bufA,DDIM,128,
                                       nullptr,nullptr,0, EE, 0);
    sgemm<<<dim3(1,NTOK/128,JJ),256>>>(src,DDIM,EE, wkt,EE,(long)128*128, bufB,DDIM,128,
                                       nullptr,nullptr,0, EE, 0);
    sgemm<<<dim3(1,NTOK/128,JJ),256>>>(src,DDIM,EE, wvt,EE,(long)128*128, bufC,DDIM,128,
                                       nullptr,nullptr,0, EE, 0);

    // ---- temporal causal attention -> concat layout ----
    temporal_attn<<<dim3(JJ,HH,BB),128>>>(bufA, bufB, bufC, bufD);

    // ---- temporal projection + bias + residual(src) ----
    sgemm<<<dim3(DDIM/128,NTOK/128,1),256>>>(bufD,DDIM,0, Wp_t,DDIM,0, res1,DDIM,0,
                                             bp_t, src,DDIM, DDIM, 0);

    // ---- spatial QKV ----
    sgemm<<<dim3(1,NTOK/128,JJ),256>>>(src,DDIM,EE, wqs,EE,(long)128*128, bufA,DDIM,128,
                                       nullptr,nullptr,0, EE, 0);
    // shared K/V: one big GEMM over all (b,t,j) rows
    sgemm<<<dim3(1,(NTOK*JJ)/128,1),256>>>(src,EE,0, Wk_s,EE,0, bufB,EE,0,
                                           nullptr,nullptr,0, EE, 0);
    sgemm<<<dim3(1,(NTOK*JJ)/128,1),256>>>(src,EE,0, Wv_s,EE,0, bufC,EE,0,
                                           nullptr,nullptr,0, EE, 0);

    // ---- spatial attention -> concat layout ----
    spatial_attn<<<NTOK,256>>>(bufA, bufB, bufC, bufD);

    // ---- spatial projection + bias + residual(src) ----
    sgemm<<<dim3(DDIM/128,NTOK/128,1),256>>>(bufD,DDIM,0, Wp_s,DDIM,0, res2,DDIM,0,
                                             bp_s, src,DDIM, DDIM, 0);

    // ---- BN stats for both branches ----
    bn_stats1<<<dim3(DDIM/256,NROWCH),256>>>(res1, ps, ps2);
    bn_stats2<<<DDIM/256,256>>>(ps, ps2, mean, var);
    bn_stats1<<<dim3(DDIM/256,NROWCH),256>>>(res2, ps, ps2);
    bn_stats2<<<DDIM/256,256>>>(ps, ps2, mean + DDIM, var + DDIM);

    // ---- att = bn_t + bn_s ----
    combine_att<<<(NEL+255)/256,256>>>(res1, res2, g_t, b_t, g_s, b_s, mean, var, bufA);

    // ---- FFN ----
    sgemm<<<dim3(FFD/128,NTOK/128,1),256>>>(bufA,DDIM,0, W1,DDIM,0, h1,FFD,0,
                                            b1, nullptr,0, DDIM, 1);
    sgemm<<<dim3(DDIM/128,NTOK/128,1),256>>>(h1,FFD,0, W2,FFD,0, bufB,DDIM,0,
                                             b2, bufA,DDIM, FFD, 0);

    // ---- final BN ----
    bn_stats1<<<dim3(DDIM/256,NROWCH),256>>>(bufB, ps, ps2);
    bn_stats2<<<DDIM/256,256>>>(ps, ps2, mean + 2*DDIM, var + 2*DDIM);
    final_bn<<<(NEL+255)/256,256>>>(bufB, g_f, b_f, mean + 2*DDIM, var + 2*DDIM, out);
}

// round 3
// speedup vs baseline: 1.8756x; 1.8756x over previous
#include <cuda_runtime.h>
#include <cuda_bf16.h>
#include <stdint.h>
#include <math.h>

#define BB   32
#define TT   120
#define JJ   24
#define EE   128
#define HH   8
#define DH   16
#define DDIM 3072
#define FFD  256
#define NTOK (BB*TT)            // 3840
#define NEL  (NTOK*DDIM)        // 11,796,480
#define NROWCH 30
#define WELEM (HH*JJ*DH*EE)     // 393216

typedef __nv_bfloat16 bf16;

// ===================== PTX helpers (portable, no 'a'-suffix features) =====================
__device__ __forceinline__ uint32_t smem_u32(const void* p) {
    uint32_t a;
    asm("{ .reg .u64 t; cvta.to.shared.u64 t, %1; cvt.u32.u64 %0, t; }" : "=r"(a) : "l"(p));
    return a;
}
__device__ __forceinline__ void ldmx4(uint32_t* r, uint32_t addr) {
    asm volatile("ldmatrix.sync.aligned.m8n8.x4.shared.b16 {%0,%1,%2,%3}, [%4];"
        : "=r"(r[0]), "=r"(r[1]), "=r"(r[2]), "=r"(r[3]) : "r"(addr));
}
__device__ __forceinline__ void mma16816(float* c, const uint32_t* a, uint32_t b0, uint32_t b1) {
    asm volatile("mma.sync.aligned.m16n8k16.row.col.f32.bf16.bf16.f32 "
        "{%0,%1,%2,%3}, {%4,%5,%6,%7}, {%8,%9}, {%0,%1,%2,%3};"
        : "+f"(c[0]), "+f"(c[1]), "+f"(c[2]), "+f"(c[3])
        : "r"(a[0]), "r"(a[1]), "r"(a[2]), "r"(a[3]), "r"(b0), "r"(b1));
}

// ===================== scratch (device globals) =====================
__device__ __align__(16) float g_bufA[NEL];
__device__ __align__(16) float g_bufB[NEL];
__device__ __align__(16) float g_bufC[NEL];
__device__ __align__(16) float g_res1[NEL];
__device__ __align__(16) float g_res2[NEL];
__device__ __align__(16) float g_att [NEL];
__device__ __align__(16) bf16 g_src_hi[NEL], g_src_lo[NEL];
__device__ __align__(16) bf16 g_cat_hi[NEL], g_cat_lo[NEL];
__device__ __align__(16) bf16 g_att_hi[NEL], g_att_lo[NEL];
__device__ __align__(16) bf16 g_h1_hi[NTOK*FFD], g_h1_lo[NTOK*FFD];
__device__ __align__(16) bf16 g_wqt_hi[WELEM], g_wqt_lo[WELEM];
__device__ __align__(16) bf16 g_wkt_hi[WELEM], g_wkt_lo[WELEM];
__device__ __align__(16) bf16 g_wvt_hi[WELEM], g_wvt_lo[WELEM];
__device__ __align__(16) bf16 g_wqs_hi[WELEM], g_wqs_lo[WELEM];
__device__ __align__(16) bf16 g_wks_hi[HH*DH*EE], g_wks_lo[HH*DH*EE];
__device__ __align__(16) bf16 g_wvs_hi[HH*DH*EE], g_wvs_lo[HH*DH*EE];
__device__ __align__(16) bf16 g_wpt_hi[DDIM*DDIM], g_wpt_lo[DDIM*DDIM];
__device__ __align__(16) bf16 g_wps_hi[DDIM*DDIM], g_wps_lo[DDIM*DDIM];
__device__ __align__(16) bf16 g_w1_hi[FFD*DDIM], g_w1_lo[FFD*DDIM];
__device__ __align__(16) bf16 g_w2_hi[DDIM*FFD], g_w2_lo[DDIM*FFD];
__device__ float g_ps [NROWCH*DDIM];
__device__ float g_ps2[NROWCH*DDIM];
__device__ float g_mean[3*DDIM];
__device__ float g_var [3*DDIM];

// ===================== fp32 -> bf16 hi/lo split =====================
__device__ __forceinline__ void split1(float x, bf16& h, bf16& l) {
    h = __float2bfloat16(x);
    l = __float2bfloat16(x - __bfloat162float(h));
}

__global__ __launch_bounds__(256) void split4(const float* __restrict__ in,
                                              bf16* __restrict__ hi, bf16* __restrict__ lo, long n4) {
    long i = (long)blockIdx.x*256 + threadIdx.x;
    if (i >= n4) return;
    float4 x = ((const float4*)in)[i];
    __nv_bfloat162 h01, h23, l01, l23;
    split1(x.x, h01.x, l01.x);
    split1(x.y, h01.y, l01.y);
    split1(x.z, h23.x, l23.x);
    split1(x.w, h23.y, l23.y);
    ((__nv_bfloat162*)hi)[2*i]   = h01;
    ((__nv_bfloat162*)hi)[2*i+1] = h23;
    ((__nv_bfloat162*)lo)[2*i]   = l01;
    ((__nv_bfloat162*)lo)[2*i+1] = l23;
}

// repack (H,J,d,E) -> (J, H*d, E) + split
__global__ __launch_bounds__(256) void repack_split(const float* __restrict__ in,
                                                    bf16* __restrict__ hi, bf16* __restrict__ lo) {
    int idx = blockIdx.x*256 + threadIdx.x;
    if (idx >= WELEM) return;
    int e  = idx & 127;
    int r  = idx >> 7;
    int dd = r & 15;
    int hj = r >> 4;
    int j  = hj % JJ;
    int h  = hj / JJ;
    int o  = (j*128 + h*16 + dd)*128 + e;
    float x = in[idx];
    bf16 hh, ll; split1(x, hh, ll);
    hi[o] = hh; lo[o] = ll;
}

// ===================== mma.sync bf16-split GEMM =====================
// C[M,N] = A[M,K] * B[N,K]^T via Ahi*Bhi + Ahi*Blo + Alo*Bhi (fp32 acc)
// CTA tile 128x128, BK=32, 8 warps each 32(m) x 64(n).
#define PAD 40   // row padding: 40 bf16 = 80 B -> conflict-free ldmatrix
__global__ __launch_bounds__(256, 1) void tgemm(
    const bf16* __restrict__ Ah, const bf16* __restrict__ Al, long lda, long sAz,
    const bf16* __restrict__ Bh, const bf16* __restrict__ Bl, long ldb, long sBz,
    float* C, long ldc, long sCz,
    bf16* Ch, bf16* Cl,
    const float* __restrict__ bias,
    const float* __restrict__ res, long ldres,
    int K, int relu, int outmode)
{
    __shared__ __align__(16) bf16 sAh[128][PAD];
    __shared__ __align__(16) bf16 sAl[128][PAD];
    __shared__ __align__(16) bf16 sBh[128][PAD];
    __shared__ __align__(16) bf16 sBl[128][PAD];

    const int tid = threadIdx.x;
    const int wid = tid >> 5, lid = tid & 31;
    const int wm = wid & 3;      // 0..3 -> 32 rows each
    const int wn = wid >> 2;     // 0..1 -> 64 cols each

    const bf16* Abh = Ah + (long)blockIdx.z*sAz + (long)blockIdx.y*128*lda;
    const bf16* Abl = Al + (long)blockIdx.z*sAz + (long)blockIdx.y*128*lda;
    const bf16* Bbh = Bh + (long)blockIdx.z*sBz + (long)blockIdx.x*128*ldb;
    const bf16* Bbl = Bl + (long)blockIdx.z*sBz + (long)blockIdx.x*128*ldb;

    float acc[2][8][4];
    #pragma unroll
    for (int mt = 0; mt < 2; mt++)
        #pragma unroll
        for (int nt = 0; nt < 8; nt++)
            #pragma unroll
            for (int c = 0; c < 4; c++) acc[mt][nt][c] = 0.f;

    const int NC = K >> 5;   // K-chunks of 32
    uint4 pf[8];

    // preload chunk 0
    {
        #pragma unroll
        for (int i = 0; i < 2; i++) {
            int s = tid + i*256;
            long row = s >> 2;
            int  g   = s & 3;
            long oA = row*lda + g*8;
            long oB = row*ldb + g*8;
            pf[i*4+0] = *(const uint4*)(Abh + oA);
            pf[i*4+1] = *(const uint4*)(Abl + oA);
            pf[i*4+2] = *(const uint4*)(Bbh + oB);
            pf[i*4+3] = *(const uint4*)(Bbl + oB);
        }
    }

    for (int kc = 0; kc < NC; kc++) {
        __syncthreads();
        #pragma unroll
        for (int i = 0; i < 2; i++) {
            int s = tid + i*256;
            int row = s >> 2;
            int g   = s & 3;
            *(uint4*)&sAh[row][g*8] = pf[i*4+0];
            *(uint4*)&sAl[row][g*8] = pf[i*4+1];
            *(uint4*)&sBh[row][g*8] = pf[i*4+2];
            *(uint4*)&sBl[row][g*8] = pf[i*4+3];
        }
        __syncthreads();

        if (kc + 1 < NC) {
            long kof = (long)(kc + 1) * 32;
            #pragma unroll
            for (int i = 0; i < 2; i++) {
                int s = tid + i*256;
                long row = s >> 2;
                int  g   = s & 3;
                long oA = row*lda + kof + g*8;
                long oB = row*ldb + kof + g*8;
                pf[i*4+0] = *(const uint4*)(Abh + oA);
                pf[i*4+1] = *(const uint4*)(Abl + oA);
                pf[i*4+2] = *(const uint4*)(Bbh + oB);
                pf[i*4+3] = *(const uint4*)(Bbl + oB);
            }
        }

        #pragma unroll
        for (int kk = 0; kk < 2; kk++) {
            const int fc = kk*16 + (lid >> 4)*8;   // k col for ldmatrix lane
            const int fr = lid & 15;               // row-within-16 for ldmatrix lane
            uint32_t ah[2][4], al[2][4];
            #pragma unroll
            for (int mt = 0; mt < 2; mt++) {
                int r = wm*32 + mt*16 + fr;
                ldmx4(ah[mt], smem_u32(&sAh[r][fc]));
                ldmx4(al[mt], smem_u32(&sAl[r][fc]));
            }
            #pragma unroll
            for (int p = 0; p < 4; p++) {
                int rn = wn*64 + p*16 + fr;
                uint32_t bh[4], bl[4];
                ldmx4(bh, smem_u32(&sBh[rn][fc]));
                ldmx4(bl, smem_u32(&sBl[rn][fc]));
                #pragma unroll
                for (int mt = 0; mt < 2; mt++) {
                    mma16816(acc[mt][2*p+0], ah[mt], bh[0], bh[2]);
                    mma16816(acc[mt][2*p+1], ah[mt], bh[1], bh[3]);
                    mma16816(acc[mt][2*p+0], ah[mt], bl[0], bl[2]);
                    mma16816(acc[mt][2*p+1], ah[mt], bl[1], bl[3]);
                    mma16816(acc[mt][2*p+0], al[mt], bh[0], bh[2]);
                    mma16816(acc[mt][2*p+1], al[mt], bh[1], bh[3]);
                }
            }
        }
    }

    // ---- epilogue ----
    const int qr = lid >> 2;          // 0..7
    const int qc = (lid & 3) * 2;     // 0,2,4,6
    #pragma unroll
    for (int mt = 0; mt < 2; mt++) {
        #pragma unroll
        for (int half = 0; half < 2; half++) {   // c0/c1 vs c2/c3 (row, row+8)
            long m = (long)blockIdx.y*128 + wm*32 + mt*16 + qr + half*8;
            #pragma unroll
            for (int nt = 0; nt < 8; nt++) {
                long n = (long)blockIdx.x*128 + wn*64 + nt*8 + qc;
                float v0 = acc[mt][nt][half*2+0];
                float v1 = acc[mt][nt][half*2+1];
                if (bias) { v0 += bias[n]; v1 += bias[n+1]; }
                if (res)  { v0 += res[m*ldres + n]; v1 += res[m*ldres + n + 1]; }
                if (relu) { v0 = fmaxf(v0, 0.f); v1 = fmaxf(v1, 0.f); }
                if (outmode == 0) {
                    float* Cp = C + (long)blockIdx.z*sCz + m*ldc + n;
                    Cp[0] = v0; Cp[1] = v1;
                } else {
                    long off = m*ldc + n;
                    bf16 h0, l0, h1, l1;
                    split1(v0, h0, l0);
                    split1(v1, h1, l1);
                    Ch[off] = h0; Ch[off+1] = h1;
                    Cl[off] = l0; Cl[off+1] = l1;
                }
            }
        }
    }
}

// ===================== temporal attention =====================
__global__ __launch_bounds__(128) void temporal_attn(
    const float* __restrict__ q, const float* __restrict__ k,
    const float* __restrict__ v, bf16* __restrict__ oh, bf16* __restrict__ ol)
{
    int j = blockIdx.x, h = blockIdx.y, b = blockIdx.z;
    __shared__ float Ks[TT][DH];
    __shared__ float Vs[TT][DH];
    int tid = threadIdx.x;
    for (int idx = tid; idx < TT*DH; idx += 128) {
        int t = idx >> 4, dd = idx & 15;
        long off = ((long)(b*TT + t)*JJ + j)*128 + h*DH + dd;
        Ks[t][dd] = k[off];
        Vs[t][dd] = v[off];
    }
    __syncthreads();
    int t = tid;
    if (t < TT) {
        float qr[DH];
        long qoff = ((long)(b*TT + t)*JJ + j)*128 + h*DH;
        #pragma unroll
        for (int dd = 0; dd < DH; dd++) qr[dd] = q[qoff + dd];
        float m = -1e30f, l = 0.f, acc[DH];
        #pragma unroll
        for (int dd = 0; dd < DH; dd++) acc[dd] = 0.f;
        for (int s = 0; s <= t; s++) {
            float sc = 0.f;
            #pragma unroll
            for (int dd = 0; dd < DH; dd++) sc = fmaf(qr[dd], Ks[s][dd], sc);
            sc *= 0.25f;
            float mn = fmaxf(m, sc);
            float corr = __expf(m - mn);
            float p    = __expf(sc - mn);
            l = l*corr + p;
            #pragma unroll
            for (int dd = 0; dd < DH; dd++) acc[dd] = fmaf(acc[dd], corr, p*Vs[s][dd]);
            m = mn;
        }
        float inv = 1.f / l;
        long ooff = (long)(b*TT + t)*DDIM + h*(JJ*DH) + j*DH;
        #pragma unroll
        for (int dd = 0; dd < DH; dd++) {
            bf16 hh, ll; split1(acc[dd]*inv, hh, ll);
            oh[ooff + dd] = hh; ol[ooff + dd] = ll;
        }
    }
}

// ===================== spatial attention =====================
__global__ __launch_bounds__(256) void spatial_attn(
    const float* __restrict__ q, const float* __restrict__ k,
    const float* __restrict__ v, bf16* __restrict__ oh, bf16* __restrict__ ol)
{
    int tok  = blockIdx.x;
    int h    = threadIdx.x >> 5;
    int lane = threadIdx.x & 31;
    __shared__ float Ks[HH][JJ][DH];
    __shared__ float Vs[HH][JJ][DH];
    for (int idx = lane; idx < JJ*DH; idx += 32) {
        int jj = idx >> 4, dd = idx & 15;
        long off = ((long)tok*JJ + jj)*128 + h*DH + dd;
        Ks[h][jj][dd] = k[off];
        Vs[h][jj][dd] = v[off];
    }
    __syncwarp();
    if (lane < JJ) {
        int j = lane;
        float qr[DH];
        long qoff = ((long)tok*JJ + j)*128 + h*DH;
        #pragma unroll
        for (int dd = 0; dd < DH; dd++) qr[dd] = q[qoff + dd];
        float s[JJ];
        float m = -1e30f;
        #pragma unroll
        for (int kk = 0; kk < JJ; kk++) {
            float sc = 0.f;
            #pragma unroll
            for (int dd = 0; dd < DH; dd++) sc = fmaf(qr[dd], Ks[h][kk][dd], sc);
            sc *= 0.25f;
            s[kk] = sc;
            m = fmaxf(m, sc);
        }
        float l = 0.f;
        #pragma unroll
        for (int kk = 0; kk < JJ; kk++) { s[kk] = __expf(s[kk] - m); l += s[kk]; }
        float acc[DH];
        #pragma unroll
        for (int dd = 0; dd < DH; dd++) acc[dd] = 0.f;
        #pragma unroll
        for (int kk = 0; kk < JJ; kk++)
            #pragma unroll
            for (int dd = 0; dd < DH; dd++) acc[dd] = fmaf(s[kk], Vs[h][kk][dd], acc[dd]);
        float inv = 1.f / l;
        long ooff = (long)tok*DDIM + h*(JJ*DH) + j*DH;
        #pragma unroll
        for (int dd = 0; dd < DH; dd++) {
            bf16 hh, ll; split1(acc[dd]*inv, hh, ll);
            oh[ooff + dd] = hh; ol[ooff + dd] = ll;
        }
    }
}

// ===================== BN stats (deterministic) =====================
__global__ __launch_bounds__(256) void bn_stats1(
    const float* __restrict__ in, float* __restrict__ ps, float* __restrict__ ps2)
{
    int c = blockIdx.x*256 + threadIdx.x;
    const float* p = in + (long)blockIdx.y*128*DDIM + c;
    float s = 0.f, s2 = 0.f;
    #pragma unroll 4
    for (int r = 0; r < 128; r++) {
        float x = p[(long)r*DDIM];
        s  += x;
        s2 = fmaf(x, x, s2);
    }
    ps [blockIdx.y*DDIM + c] = s;
    ps2[blockIdx.y*DDIM + c] = s2;
}
__global__ __launch_bounds__(256) void bn_stats2(
    const float* __restrict__ ps, const float* __restrict__ ps2,
    float* __restrict__ mean, float* __restrict__ var)
{
    int c = blockIdx.x*256 + threadIdx.x;
    float s = 0.f, s2 = 0.f;
    #pragma unroll
    for (int r = 0; r < NROWCH; r++) { s += ps[r*DDIM + c]; s2 += ps2[r*DDIM + c]; }
    float m = s / (float)NTOK;
    mean[c] = m;
    var[c]  = s2 / (float)NTOK - m*m;
}

// att = bn_t(res1) + bn_s(res2); also emit bf16 hi/lo for FFN
__global__ __launch_bounds__(256) void combine_att(
    const float* __restrict__ x1, const float* __restrict__ x2,
    const float* __restrict__ gt, const float* __restrict__ bt,
    const float* __restrict__ gs, const float* __restrict__ bs,
    const float* __restrict__ mean, const float* __restrict__ var,
    float* __restrict__ out, bf16* __restrict__ oh, bf16* __restrict__ ol)
{
    long i = (long)blockIdx.x*256 + threadIdx.x;
    if (i >= NEL) return;
    int c = (int)(i % DDIM);
    float a = (x1[i] - mean[c])        * rsqrtf(var[c]        + 1e-5f) * gt[c] + bt[c];
    float b = (x2[i] - mean[DDIM + c]) * rsqrtf(var[DDIM + c] + 1e-5f) * gs[c] + bs[c];
    float s = a + b;
    out[i] = s;
    bf16 hh, ll; split1(s, hh, ll);
    oh[i] = hh; ol[i] = ll;
}

__global__ __launch_bounds__(256) void final_bn(
    const float* __restrict__ x,
    const float* __restrict__ gf, const float* __restrict__ bf,
    const float* __restrict__ mean, const float* __restrict__ var,
    float* __restrict__ out)
{
    long i = (long)blockIdx.x*256 + threadIdx.x;
    if (i >= NEL) return;
    int c = (int)(i % DDIM);
    out[i] = (x[i] - mean[c]) * rsqrtf(var[c] + 1e-5f) * gf[c] + bf[c];
}

// ===================== launch =====================
extern "C" void kernel_launch(void* const* d_in, const int* in_sizes, int n_in,
                              void* d_out, int out_size)
{
    const float* src  = (const float*)d_in[0];
    const float* Wq_t = (const float*)d_in[1];
    const float* Wk_t = (const float*)d_in[2];
    const float* Wv_t = (const float*)d_in[3];
    const float* Wp_t = (const float*)d_in[4];
    const float* bp_t = (const float*)d_in[5];
    const float* g_t  = (const float*)d_in[6];
    const float* b_t  = (const float*)d_in[7];
    const float* Wq_s = (const float*)d_in[8];
    const float* Wk_s = (const float*)d_in[9];
    const float* Wv_s = (const float*)d_in[10];
    const float* Wp_s = (const float*)d_in[11];
    const float* bp_s = (const float*)d_in[12];
    const float* g_s  = (const float*)d_in[13];
    const float* b_s  = (const float*)d_in[14];
    const float* W1   = (const float*)d_in[15];
    const float* b1   = (const float*)d_in[16];
    const float* W2   = (const float*)d_in[17];
    const float* b2   = (const float*)d_in[18];
    const float* g_f  = (const float*)d_in[19];
    const float* b_f  = (const float*)d_in[20];
    float* out = (float*)d_out;

    float *bufA,*bufB,*bufC,*res1,*res2,*att,*ps,*ps2,*mean,*var;
    bf16 *src_hi,*src_lo,*cat_hi,*cat_lo,*att_hi,*att_lo,*h1_hi,*h1_lo;
    bf16 *wqt_hi,*wqt_lo,*wkt_hi,*wkt_lo,*wvt_hi,*wvt_lo,*wqs_hi,*wqs_lo;
    bf16 *wks_hi,*wks_lo,*wvs_hi,*wvs_lo,*wpt_hi,*wpt_lo,*wps_hi,*wps_lo;
    bf16 *w1_hi,*w1_lo,*w2_hi,*w2_lo;
    cudaGetSymbolAddress((void**)&bufA, g_bufA);
    cudaGetSymbolAddress((void**)&bufB, g_bufB);
    cudaGetSymbolAddress((void**)&bufC, g_bufC);
    cudaGetSymbolAddress((void**)&res1, g_res1);
    cudaGetSymbolAddress((void**)&res2, g_res2);
    cudaGetSymbolAddress((void**)&att,  g_att);
    cudaGetSymbolAddress((void**)&ps,   g_ps);
    cudaGetSymbolAddress((void**)&ps2,  g_ps2);
    cudaGetSymbolAddress((void**)&mean, g_mean);
    cudaGetSymbolAddress((void**)&var,  g_var);
    cudaGetSymbolAddress((void**)&src_hi, g_src_hi); cudaGetSymbolAddress((void**)&src_lo, g_src_lo);
    cudaGetSymbolAddress((void**)&cat_hi, g_cat_hi); cudaGetSymbolAddress((void**)&cat_lo, g_cat_lo);
    cudaGetSymbolAddress((void**)&att_hi, g_att_hi); cudaGetSymbolAddress((void**)&att_lo, g_att_lo);
    cudaGetSymbolAddress((void**)&h1_hi,  g_h1_hi);  cudaGetSymbolAddress((void**)&h1_lo,  g_h1_lo);
    cudaGetSymbolAddress((void**)&wqt_hi, g_wqt_hi); cudaGetSymbolAddress((void**)&wqt_lo, g_wqt_lo);
    cudaGetSymbolAddress((void**)&wkt_hi, g_wkt_hi); cudaGetSymbolAddress((void**)&wkt_lo, g_wkt_lo);
    cudaGetSymbolAddress((void**)&wvt_hi, g_wvt_hi); cudaGetSymbolAddress((void**)&wvt_lo, g_wvt_lo);
    cudaGetSymbolAddress((void**)&wqs_hi, g_wqs_hi); cudaGetSymbolAddress((void**)&wqs_lo, g_wqs_lo);
    cudaGetSymbolAddress((void**)&wks_hi, g_wks_hi); cudaGetSymbolAddress((void**)&wks_lo, g_wks_lo);
    cudaGetSymbolAddress((void**)&wvs_hi, g_wvs_hi); cudaGetSymbolAddress((void**)&wvs_lo, g_wvs_lo);
    cudaGetSymbolAddress((void**)&wpt_hi, g_wpt_hi); cudaGetSymbolAddress((void**)&wpt_lo, g_wpt_lo);
    cudaGetSymbolAddress((void**)&wps_hi, g_wps_hi); cudaGetSymbolAddress((void**)&wps_lo, g_wps_lo);
    cudaGetSymbolAddress((void**)&w1_hi,  g_w1_hi);  cudaGetSymbolAddress((void**)&w1_lo,  g_w1_lo);
    cudaGetSymbolAddress((void**)&w2_hi,  g_w2_hi);  cudaGetSymbolAddress((void**)&w2_lo,  g_w2_lo);

    // ---- conversions / repacks ----
    split4<<<(NEL/4 + 255)/256, 256>>>(src, src_hi, src_lo, NEL/4);
    repack_split<<<(WELEM + 255)/256, 256>>>(Wq_t, wqt_hi, wqt_lo);
    repack_split<<<(WELEM + 255)/256, 256>>>(Wk_t, wkt_hi, wkt_lo);
    repack_split<<<(WELEM + 255)/256, 256>>>(Wv_t, wvt_hi, wvt_lo);
    repack_split<<<(WELEM + 255)/256, 256>>>(Wq_s, wqs_hi, wqs_lo);
    split4<<<(HH*DH*EE/4 + 255)/256, 256>>>(Wk_s, wks_hi, wks_lo, HH*DH*EE/4);
    split4<<<(HH*DH*EE/4 + 255)/256, 256>>>(Wv_s, wvs_hi, wvs_lo, HH*DH*EE/4);
    split4<<<(DDIM*DDIM/4 + 255)/256, 256>>>(Wp_t, wpt_hi, wpt_lo, (long)DDIM*DDIM/4);
    split4<<<(DDIM*DDIM/4 + 255)/256, 256>>>(Wp_s, wps_hi, wps_lo, (long)DDIM*DDIM/4);
    split4<<<(FFD*DDIM/4 + 255)/256, 256>>>(W1, w1_hi, w1_lo, (long)FFD*DDIM/4);
    split4<<<(FFD*DDIM/4 + 255)/256, 256>>>(W2, w2_hi, w2_lo, (long)FFD*DDIM/4);

    // ---- temporal QKV (batched over joints, z=24): M=3840, N=128, K=128 ----
    tgemm<<<dim3(1, NTOK/128, JJ), 256>>>(
        src_hi, src_lo, DDIM, 128, wqt_hi, wqt_lo, EE, 16384,
        bufA, DDIM, 128, nullptr, nullptr, nullptr, nullptr, 0, EE, 0, 0);
    tgemm<<<dim3(1, NTOK/128, JJ), 256>>>(
        src_hi, src_lo, DDIM, 128, wkt_hi, wkt_lo, EE, 16384,
        bufB, DDIM, 128, nullptr, nullptr, nullptr, nullptr, 0, EE, 0, 0);
    tgemm<<<dim3(1, NTOK/128, JJ), 256>>>(
        src_hi, src_lo, DDIM, 128, wvt_hi, wvt_lo, EE, 16384,
        bufC, DDIM, 128, nullptr, nullptr, nullptr, nullptr, 0, EE, 0, 0);

    // ---- temporal attention -> concat (bf16 hi/lo) ----
    temporal_attn<<<dim3(JJ, HH, BB), 128>>>(bufA, bufB, bufC, cat_hi, cat_lo);

    // ---- temporal projection + bias + residual ----
    tgemm<<<dim3(DDIM/128, NTOK/128, 1), 256>>>(
        cat_hi, cat_lo, DDIM, 0, wpt_hi, wpt_lo, DDIM, 0,
        res1, DDIM, 0, nullptr, nullptr, bp_t, src, DDIM, DDIM, 0, 0);

    // ---- spatial QKV ----
    tgemm<<<dim3(1, NTOK/128, JJ), 256>>>(
        src_hi, src_lo, DDIM, 128, wqs_hi, wqs_lo, EE, 16384,
        bufA, DDIM, 128, nullptr, nullptr, nullptr, nullptr, 0, EE, 0, 0);
    tgemm<<<dim3(1, (NTOK*JJ)/128, 1), 256>>>(
        src_hi, src_lo, EE, 0, wks_hi, wks_lo, EE, 0,
        bufB, EE, 0, nullptr, nullptr, nullptr, nullptr, 0, EE, 0, 0);
    tgemm<<<dim3(1, (NTOK*JJ)/128, 1), 256>>>(
        src_hi, src_lo, EE, 0, wvs_hi, wvs_lo, EE, 0,
        bufC, EE, 0, nullptr, nullptr, nullptr, nullptr, 0, EE, 0, 0);

    // ---- spatial attention -> concat ----
    spatial_attn<<<NTOK, 256>>>(bufA, bufB, bufC, cat_hi, cat_lo);

    // ---- spatial projection + bias + residual ----
    tgemm<<<dim3(DDIM/128, NTOK/128, 1), 256>>>(
        cat_hi, cat_lo, DDIM, 0, wps_hi, wps_lo, DDIM, 0,
        res2, DDIM, 0, nullptr, nullptr, bp_s, src, DDIM, DDIM, 0, 0);

    // ---- BN stats ----
    bn_stats1<<<dim3(DDIM/256, NROWCH), 256>>>(res1, ps, ps2);
    bn_stats2<<<DDIM/256, 256>>>(ps, ps2, mean, var);
    bn_stats1<<<dim3(DDIM/256, NROWCH), 256>>>(res2, ps, ps2);
    bn_stats2<<<DDIM/256, 256>>>(ps, ps2, mean + DDIM, var + DDIM);

    // ---- att = bn_t + bn_s (fp32 + bf16 hi/lo) ----
    combine_att<<<(NEL + 255)/256, 256>>>(res1, res2, g_t, b_t, g_s, b_s,
                                          mean, var, att, att_hi, att_lo);

    // ---- FFN: W1 (relu, bf16 out), W2 (+bias +residual att) ----
    tgemm<<<dim3(FFD/128, NTOK/128, 1), 256>>>(
        att_hi, att_lo, DDIM, 0, w1_hi, w1_lo, DDIM, 0,
        nullptr, FFD, 0, h1_hi, h1_lo, b1, nullptr, 0, DDIM, 1, 1);
    tgemm<<<dim3(DDIM/128, NTOK/128, 1), 256>>>(
        h1_hi, h1_lo, FFD, 0, w2_hi, w2_lo, FFD, 0,
        bufA, DDIM, 0, nullptr, nullptr, b2, att, DDIM, FFD, 0, 0);

    // ---- final BN ----
    bn_stats1<<<dim3(DDIM/256, NROWCH), 256>>>(bufA, ps, ps2);
    bn_stats2<<<DDIM/256, 256>>>(ps, ps2, mean + 2*DDIM, var + 2*DDIM);
    final_bn<<<(NEL + 255)/256, 256>>>(bufA, g_f, b_f, mean + 2*DDIM, var + 2*DDIM, out);
}

// round 4
// speedup vs baseline: 4.0293x; 2.1483x over previous
#include <cuda_runtime.h>
#include <cuda_fp16.h>
#include <stdint.h>
#include <math.h>

#define BB   32
#define TT   120
#define JJ   24
#define EE   128
#define HH   8
#define DH   16
#define DDIM 3072
#define FFD  256
#define NTOK (BB*TT)            // 3840
#define NEL  (NTOK*DDIM)        // 11,796,480
#define NROWCH 30
#define WELEM (HH*JJ*DH*EE)     // 393216

typedef __half fp16;

// ===================== PTX helpers (portable) =====================
__device__ __forceinline__ uint32_t smem_u32(const void* p) {
    uint32_t a;
    asm("{ .reg .u64 t; cvta.to.shared.u64 t, %1; cvt.u32.u64 %0, t; }" : "=r"(a) : "l"(p));
    return a;
}
__device__ __forceinline__ void ldmx4(uint32_t* r, uint32_t addr) {
    asm volatile("ldmatrix.sync.aligned.m8n8.x4.shared.b16 {%0,%1,%2,%3}, [%4];"
        : "=r"(r[0]), "=r"(r[1]), "=r"(r[2]), "=r"(r[3]) : "r"(addr));
}
__device__ __forceinline__ void mma16816(float* c, const uint32_t* a, uint32_t b0, uint32_t b1) {
    asm volatile("mma.sync.aligned.m16n8k16.row.col.f32.f16.f16.f32 "
        "{%0,%1,%2,%3}, {%4,%5,%6,%7}, {%8,%9}, {%0,%1,%2,%3};"
        : "+f"(c[0]), "+f"(c[1]), "+f"(c[2]), "+f"(c[3])
        : "r"(a[0]), "r"(a[1]), "r"(a[2]), "r"(a[3]), "r"(b0), "r"(b1));
}
__device__ __forceinline__ void cpa16(uint32_t saddr, const void* g) {
    asm volatile("cp.async.ca.shared.global [%0], [%1], 16;" :: "r"(saddr), "l"(g));
}
#define CPA_COMMIT() asm volatile("cp.async.commit_group;" ::: "memory")
#define CPA_WAIT0()  asm volatile("cp.async.wait_group 0;" ::: "memory")
#define CPA_WAIT1()  asm volatile("cp.async.wait_group 1;" ::: "memory")

// ===================== scratch (device globals) =====================
__device__ __align__(16) float g_qkv[NTOK*JJ*384];   // temporal q,k,v
__device__ __align__(16) float g_kv [NTOK*JJ*256];   // spatial k,v
__device__ __align__(16) float g_q  [NEL];           // spatial q / ffn out
__device__ __align__(16) float g_res1[NEL];
__device__ __align__(16) float g_res2[NEL];
__device__ __align__(16) float g_att [NEL];
__device__ __align__(16) fp16 g_src_h[NEL];
__device__ __align__(16) fp16 g_cat_h[NEL];
__device__ __align__(16) fp16 g_att_h[NEL];
__device__ __align__(16) fp16 g_h1_h[NTOK*FFD];
__device__ __align__(16) fp16 g_wqkv_t[JJ*384*EE];
__device__ __align__(16) fp16 g_wq_s[WELEM];
__device__ __align__(16) fp16 g_wkv_s[2*HH*DH*EE];
__device__ __align__(16) fp16 g_wpt_h[DDIM*DDIM];
__device__ __align__(16) fp16 g_wps_h[DDIM*DDIM];
__device__ __align__(16) fp16 g_w1_h[FFD*DDIM];
__device__ __align__(16) fp16 g_w2_h[DDIM*FFD];
__device__ float g_ps [NROWCH*DDIM];
__device__ float g_ps2[NROWCH*DDIM];
__device__ float g_mean[3*DDIM];
__device__ float g_var [3*DDIM];

// ===================== conversions =====================
__global__ __launch_bounds__(256) void cvt4(const float* __restrict__ in,
                                            fp16* __restrict__ o, long n4) {
    long i = (long)blockIdx.x*256 + threadIdx.x;
    if (i >= n4) return;
    float4 x = ((const float4*)in)[i];
    __half2 a = __floats2half2_rn(x.x, x.y);
    __half2 b = __floats2half2_rn(x.z, x.w);
    ((__half2*)o)[2*i]   = a;
    ((__half2*)o)[2*i+1] = b;
}

// temporal weights: (H,J,d,E) x3 -> [J][384][E]  (q rows 0-127, k 128-255, v 256-383)
__global__ __launch_bounds__(256) void repack_qkv_t(
    const float* __restrict__ wq, const float* __restrict__ wk,
    const float* __restrict__ wv, fp16* __restrict__ o)
{
    int idx = blockIdx.x*256 + threadIdx.x;
    if (idx >= WELEM) return;
    int e  = idx & 127;
    int r  = idx >> 7;
    int dd = r & 15;
    int hj = r >> 4;
    int j  = hj % JJ;
    int h  = hj / JJ;
    int ob = j*(384*128) + (h*16 + dd)*128 + e;
    o[ob          ] = __float2half_rn(wq[idx]);
    o[ob + 128*128] = __float2half_rn(wk[idx]);
    o[ob + 256*128] = __float2half_rn(wv[idx]);
}

// spatial q weights: (H,J,d,E) -> [J][128][E]
__global__ __launch_bounds__(256) void repack_q_s(const float* __restrict__ in, fp16* __restrict__ o) {
    int idx = blockIdx.x*256 + threadIdx.x;
    if (idx >= WELEM) return;
    int e  = idx & 127;
    int r  = idx >> 7;
    int dd = r & 15;
    int hj = r >> 4;
    int j  = hj % JJ;
    int h  = hj / JJ;
    o[j*16384 + (h*16 + dd)*128 + e] = __float2half_rn(in[idx]);
}

// spatial shared k/v: (H,d,E) each -> [256][E]
__global__ __launch_bounds__(256) void cvt_pack_kv(const float* __restrict__ wk,
                                                   const float* __restrict__ wv, fp16* __restrict__ o) {
    int idx = blockIdx.x*256 + threadIdx.x;
    int n = HH*DH*EE;
    if (idx >= n) return;
    o[idx]     = __float2half_rn(wk[idx]);
    o[idx + n] = __float2half_rn(wv[idx]);
}

// ===================== fp16 mma GEMM, cp.async double-buffered =====================
// C[M,N] = A[M,K] * B[N,K]^T, fp32 acc. CTA 128x128, BK=64, 8 warps 32x64.
#define ROWB 144              // bytes per smem row (64 halves + 8 pad)
#define ABYTES (128*ROWB)     // 18432
#define BUFBYTES (2*ABYTES)   // 36864 per stage
#define TG_SMEM (2*BUFBYTES)  // 73728
__global__ __launch_bounds__(256, 2) void tgemm(
    const fp16* __restrict__ A, long lda, long sAz,
    const fp16* __restrict__ B, long ldb, long sBz,
    float* C, long ldc, long sCz,
    fp16* Ch,
    const float* __restrict__ bias,
    const float* __restrict__ res, long ldres,
    int K, int relu, int outmode)
{
    extern __shared__ char dsm[];
    const uint32_t sbase = smem_u32(dsm);
    const int tid = threadIdx.x;
    const int wid = tid >> 5, lid = tid & 31;
    const int wm = wid & 3;      // 4 row groups of 32
    const int wn = wid >> 2;     // 2 col groups of 64

    const fp16* Ab = A + (long)blockIdx.z*sAz + (long)blockIdx.y*128*lda;
    const fp16* Bb = B + (long)blockIdx.z*sBz + (long)blockIdx.x*128*ldb;

    float acc[2][8][4];
    #pragma unroll
    for (int mt = 0; mt < 2; mt++)
        #pragma unroll
        for (int nt = 0; nt < 8; nt++)
            #pragma unroll
            for (int c = 0; c < 4; c++) acc[mt][nt][c] = 0.f;

    const int NC = K >> 6;
    const int row = tid >> 3;          // load row for this thread (x4 slots)
    const int g   = tid & 7;

    // prefetch chunk 0 -> buf 0
    {
        uint32_t sA0 = sbase, sB0 = sbase + ABYTES;
        #pragma unroll
        for (int i = 0; i < 4; i++) {
            int r = row + i*32;
            uint32_t so = (uint32_t)(r*ROWB + g*16);
            cpa16(sA0 + so, Ab + (long)r*lda + g*8);
            cpa16(sB0 + so, Bb + (long)r*ldb + g*8);
        }
        CPA_COMMIT();
    }

    for (int kc = 0; kc < NC; kc++) {
        const int b = kc & 1;
        if (kc + 1 < NC) {
            uint32_t sA0 = sbase + (b^1)*BUFBYTES, sB0 = sA0 + ABYTES;
            long kof = (long)(kc + 1)*64;
            #pragma unroll
            for (int i = 0; i < 4; i++) {
                int r = row + i*32;
                uint32_t so = (uint32_t)(r*ROWB + g*16);
                cpa16(sA0 + so, Ab + (long)r*lda + kof + g*8);
                cpa16(sB0 + so, Bb + (long)r*ldb + kof + g*8);
            }
            CPA_COMMIT();
            CPA_WAIT1();
        } else {
            CPA_WAIT0();
        }
        __syncthreads();

        const uint32_t sA0 = sbase + b*BUFBYTES, sB0 = sA0 + ABYTES;
        const int fr = lid & 15;
        #pragma unroll
        for (int kk = 0; kk < 4; kk++) {
            const uint32_t fcb = (uint32_t)((kk*16 + (lid >> 4)*8) * 2);
            uint32_t a0[4], a1[4];
            ldmx4(a0, sA0 + (uint32_t)((wm*32 + fr)*ROWB) + fcb);
            ldmx4(a1, sA0 + (uint32_t)((wm*32 + 16 + fr)*ROWB) + fcb);
            #pragma unroll
            for (int p = 0; p < 4; p++) {
                uint32_t bb[4];
                ldmx4(bb, sB0 + (uint32_t)((wn*64 + p*16 + fr)*ROWB) + fcb);
                mma16816(acc[0][2*p+0], a0, bb[0], bb[2]);
                mma16816(acc[0][2*p+1], a0, bb[1], bb[3]);
                mma16816(acc[1][2*p+0], a1, bb[0], bb[2]);
                mma16816(acc[1][2*p+1], a1, bb[1], bb[3]);
            }
        }
        __syncthreads();
    }

    // ---- epilogue ----
    const int qr = lid >> 2;
    const int qc = (lid & 3) * 2;
    #pragma unroll
    for (int mt = 0; mt < 2; mt++) {
        #pragma unroll
        for (int half = 0; half < 2; half++) {
            long m = (long)blockIdx.y*128 + wm*32 + mt*16 + qr + half*8;
            #pragma unroll
            for (int nt = 0; nt < 8; nt++) {
                long n = (long)blockIdx.x*128 + wn*64 + nt*8 + qc;
                float v0 = acc[mt][nt][half*2+0];
                float v1 = acc[mt][nt][half*2+1];
                if (bias) { v0 += bias[n]; v1 += bias[n+1]; }
                if (res)  { v0 += res[m*ldres + n]; v1 += res[m*ldres + n + 1]; }
                if (relu) { v0 = fmaxf(v0, 0.f); v1 = fmaxf(v1, 0.f); }
                if (outmode == 0) {
                    float* Cp = C + (long)blockIdx.z*sCz + m*ldc + n;
                    Cp[0] = v0; Cp[1] = v1;
                } else {
                    *(__half2*)(Ch + m*ldc + n) = __floats2half2_rn(v0, v1);
                }
            }
        }
    }
}

// ===================== temporal attention =====================
// qkv layout: [tok*9216 + j*384 + {0,128,256} + h*16 + dd]
__global__ __launch_bounds__(128) void temporal_attn(
    const float* __restrict__ qkv, fp16* __restrict__ oh)
{
    int j = blockIdx.x, h = blockIdx.y, b = blockIdx.z;
    __shared__ float Ks[TT][DH];
    __shared__ float Vs[TT][DH];
    int tid = threadIdx.x;
    for (int idx = tid; idx < TT*DH; idx += 128) {
        int t = idx >> 4, dd = idx & 15;
        long off = (long)(b*TT + t)*9216 + j*384 + h*DH + dd;
        Ks[t][dd] = qkv[off + 128];
        Vs[t][dd] = qkv[off + 256];
    }
    __syncthreads();
    int t = tid;
    if (t < TT) {
        float qr[DH];
        long qoff = (long)(b*TT + t)*9216 + j*384 + h*DH;
        #pragma unroll
        for (int dd = 0; dd < DH; dd++) qr[dd] = qkv[qoff + dd];
        float m = -1e30f, l = 0.f, acc[DH];
        #pragma unroll
        for (int dd = 0; dd < DH; dd++) acc[dd] = 0.f;
        for (int s = 0; s <= t; s++) {
            float sc = 0.f;
            #pragma unroll
            for (int dd = 0; dd < DH; dd++) sc = fmaf(qr[dd], Ks[s][dd], sc);
            sc *= 0.25f;
            float mn = fmaxf(m, sc);
            float corr = __expf(m - mn);
            float p    = __expf(sc - mn);
            l = l*corr + p;
            #pragma unroll
            for (int dd = 0; dd < DH; dd++) acc[dd] = fmaf(acc[dd], corr, p*Vs[s][dd]);
            m = mn;
        }
        float inv = 1.f / l;
        long ooff = (long)(b*TT + t)*DDIM + h*(JJ*DH) + j*DH;
        #pragma unroll
        for (int dd = 0; dd < DH; dd++) oh[ooff + dd] = __float2half_rn(acc[dd]*inv);
    }
}

// ===================== spatial attention =====================
// q: [tok*3072 + j*128 + h*16+dd]; kv: [(tok*24+j)*256 + {0,128} + h*16+dd]
__global__ __launch_bounds__(256) void spatial_attn(
    const float* __restrict__ q, const float* __restrict__ kv, fp16* __restrict__ oh)
{
    int tok  = blockIdx.x;
    int h    = threadIdx.x >> 5;
    int lane = threadIdx.x & 31;
    __shared__ float Ks[HH][JJ][DH];
    __shared__ float Vs[HH][JJ][DH];
    for (int idx = lane; idx < JJ*DH; idx += 32) {
        int jj = idx >> 4, dd = idx & 15;
        long off = ((long)tok*JJ + jj)*256 + h*DH + dd;
        Ks[h][jj][dd] = kv[off];
        Vs[h][jj][dd] = kv[off + 128];
    }
    __syncwarp();
    if (lane < JJ) {
        int j = lane;
        float qr[DH];
        long qoff = (long)tok*DDIM + j*128 + h*DH;
        #pragma unroll
        for (int dd = 0; dd < DH; dd++) qr[dd] = q[qoff + dd];
        float s[JJ];
        float m = -1e30f;
        #pragma unroll
        for (int kk = 0; kk < JJ; kk++) {
            float sc = 0.f;
            #pragma unroll
            for (int dd = 0; dd < DH; dd++) sc = fmaf(qr[dd], Ks[h][kk][dd], sc);
            sc *= 0.25f;
            s[kk] = sc;
            m = fmaxf(m, sc);
        }
        float l = 0.f;
        #pragma unroll
        for (int kk = 0; kk < JJ; kk++) { s[kk] = __expf(s[kk] - m); l += s[kk]; }
        float acc[DH];
        #pragma unroll
        for (int dd = 0; dd < DH; dd++) acc[dd] = 0.f;
        #pragma unroll
        for (int kk = 0; kk < JJ; kk++)
            #pragma unroll
            for (int dd = 0; dd < DH; dd++) acc[dd] = fmaf(s[kk], Vs[h][kk][dd], acc[dd]);
        float inv = 1.f / l;
        long ooff = (long)tok*DDIM + h*(JJ*DH) + j*DH;
        #pragma unroll
        for (int dd = 0; dd < DH; dd++) oh[ooff + dd] = __float2half_rn(acc[dd]*inv);
    }
}

// ===================== BN stats (deterministic) =====================
__global__ __launch_bounds__(256) void bn_stats1(
    const float* __restrict__ in, float* __restrict__ ps, float* __restrict__ ps2)
{
    int c = blockIdx.x*256 + threadIdx.x;
    const float* p = in + (long)blockIdx.y*128*DDIM + c;
    float s = 0.f, s2 = 0.f;
    #pragma unroll 4
    for (int r = 0; r < 128; r++) {
        float x = p[(long)r*DDIM];
        s  += x;
        s2 = fmaf(x, x, s2);
    }
    ps [blockIdx.y*DDIM + c] = s;
    ps2[blockIdx.y*DDIM + c] = s2;
}
__global__ __launch_bounds__(256) void bn_stats2(
    const float* __restrict__ ps, const float* __restrict__ ps2,
    float* __restrict__ mean, float* __restrict__ var)
{
    int c = blockIdx.x*256 + threadIdx.x;
    float s = 0.f, s2 = 0.f;
    #pragma unroll
    for (int r = 0; r < NROWCH; r++) { s += ps[r*DDIM + c]; s2 += ps2[r*DDIM + c]; }
    float m = s / (float)NTOK;
    mean[c] = m;
    var[c]  = s2 / (float)NTOK - m*m;
}

// att = bn_t(res1) + bn_s(res2); fp32 + fp16 out, vectorized x4
__global__ __launch_bounds__(256) void combine_att(
    const float* __restrict__ x1, const float* __restrict__ x2,
    const float* __restrict__ gt, const float* __restrict__ bt,
    const float* __restrict__ gs, const float* __restrict__ bs,
    const float* __restrict__ mean, const float* __restrict__ var,
    float* __restrict__ out, fp16* __restrict__ oh)
{
    long i = (long)blockIdx.x*256 + threadIdx.x;
    if (i >= NEL/4) return;
    int c0 = (int)((i*4) % DDIM);
    float4 a = ((const float4*)x1)[i];
    float4 b = ((const float4*)x2)[i];
    float r[4];
    #pragma unroll
    for (int k = 0; k < 4; k++) {
        int c = c0 + k;
        float xa = k==0?a.x:k==1?a.y:k==2?a.z:a.w;
        float xb = k==0?b.x:k==1?b.y:k==2?b.z:b.w;
        float va = (xa - mean[c])        * rsqrtf(var[c]        + 1e-5f) * gt[c] + bt[c];
        float vb = (xb - mean[DDIM + c]) * rsqrtf(var[DDIM + c] + 1e-5f) * gs[c] + bs[c];
        r[k] = va + vb;
    }
    ((float4*)out)[i] = make_float4(r[0], r[1], r[2], r[3]);
    ((__half2*)oh)[2*i]   = __floats2half2_rn(r[0], r[1]);
    ((__half2*)oh)[2*i+1] = __floats2half2_rn(r[2], r[3]);
}

__global__ __launch_bounds__(256) void final_bn(
    const float* __restrict__ x,
    const float* __restrict__ gf, const float* __restrict__ bf,
    const float* __restrict__ mean, const float* __restrict__ var,
    float* __restrict__ out)
{
    long i = (long)blockIdx.x*256 + threadIdx.x;
    if (i >= NEL/4) return;
    int c0 = (int)((i*4) % DDIM);
    float4 a = ((const float4*)x)[i];
    float r[4];
    #pragma unroll
    for (int k = 0; k < 4; k++) {
        int c = c0 + k;
        float xa = k==0?a.x:k==1?a.y:k==2?a.z:a.w;
        r[k] = (xa - mean[c]) * rsqrtf(var[c] + 1e-5f) * gf[c] + bf[c];
    }
    ((float4*)out)[i] = make_float4(r[0], r[1], r[2], r[3]);
}

// ===================== launch =====================
extern "C" void kernel_launch(void* const* d_in, const int* in_sizes, int n_in,
                              void* d_out, int out_size)
{
    const float* src  = (const float*)d_in[0];
    const float* Wq_t = (const float*)d_in[1];
    const float* Wk_t = (const float*)d_in[2];
    const float* Wv_t = (const float*)d_in[3];
    const float* Wp_t = (const float*)d_in[4];
    const float* bp_t = (const float*)d_in[5];
    const float* g_t  = (const float*)d_in[6];
    const float* b_t  = (const float*)d_in[7];
    const float* Wq_s = (const float*)d_in[8];
    const float* Wk_s = (const float*)d_in[9];
    const float* Wv_s = (const float*)d_in[10];
    const float* Wp_s = (const float*)d_in[11];
    const float* bp_s = (const float*)d_in[12];
    const float* g_s  = (const float*)d_in[13];
    const float* b_s  = (const float*)d_in[14];
    const float* W1   = (const float*)d_in[15];
    const float* b1   = (const float*)d_in[16];
    const float* W2   = (const float*)d_in[17];
    const float* b2   = (const float*)d_in[18];
    const float* g_f  = (const float*)d_in[19];
    const float* b_f  = (const float*)d_in[20];
    float* out = (float*)d_out;

    float *qkv,*kvb,*qb,*res1,*res2,*att,*ps,*ps2,*mean,*var;
    fp16 *src_h,*cat_h,*att_h,*h1_h,*wqkv_t,*wq_s,*wkv_s,*wpt_h,*wps_h,*w1_h,*w2_h;
    cudaGetSymbolAddress((void**)&qkv,  g_qkv);
    cudaGetSymbolAddress((void**)&kvb,  g_kv);
    cudaGetSymbolAddress((void**)&qb,   g_q);
    cudaGetSymbolAddress((void**)&res1, g_res1);
    cudaGetSymbolAddress((void**)&res2, g_res2);
    cudaGetSymbolAddress((void**)&att,  g_att);
    cudaGetSymbolAddress((void**)&ps,   g_ps);
    cudaGetSymbolAddress((void**)&ps2,  g_ps2);
    cudaGetSymbolAddress((void**)&mean, g_mean);
    cudaGetSymbolAddress((void**)&var,  g_var);
    cudaGetSymbolAddress((void**)&src_h,  g_src_h);
    cudaGetSymbolAddress((void**)&cat_h,  g_cat_h);
    cudaGetSymbolAddress((void**)&att_h,  g_att_h);
    cudaGetSymbolAddress((void**)&h1_h,   g_h1_h);
    cudaGetSymbolAddress((void**)&wqkv_t, g_wqkv_t);
    cudaGetSymbolAddress((void**)&wq_s,   g_wq_s);
    cudaGetSymbolAddress((void**)&wkv_s,  g_wkv_s);
    cudaGetSymbolAddress((void**)&wpt_h,  g_wpt_h);
    cudaGetSymbolAddress((void**)&wps_h,  g_wps_h);
    cudaGetSymbolAddress((void**)&w1_h,   g_w1_h);
    cudaGetSymbolAddress((void**)&w2_h,   g_w2_h);

    cudaFuncSetAttribute(tgemm, cudaFuncAttributeMaxDynamicSharedMemorySize, TG_SMEM);

    // ---- conversions / repacks ----
    cvt4<<<(NEL/4 + 255)/256, 256>>>(src, src_h, NEL/4);
    repack_qkv_t<<<(WELEM + 255)/256, 256>>>(Wq_t, Wk_t, Wv_t, wqkv_t);
    repack_q_s<<<(WELEM + 255)/256, 256>>>(Wq_s, wq_s);
    cvt_pack_kv<<<(HH*DH*EE + 255)/256, 256>>>(Wk_s, Wv_s, wkv_s);
    cvt4<<<((long)DDIM*DDIM/4 + 255)/256, 256>>>(Wp_t, wpt_h, (long)DDIM*DDIM/4);
    cvt4<<<((long)DDIM*DDIM/4 + 255)/256, 256>>>(Wp_s, wps_h, (long)DDIM*DDIM/4);
    cvt4<<<((long)FFD*DDIM/4 + 255)/256, 256>>>(W1, w1_h, (long)FFD*DDIM/4);
    cvt4<<<((long)FFD*DDIM/4 + 255)/256, 256>>>(W2, w2_h, (long)FFD*DDIM/4);

    // ---- temporal QKV: one GEMM, N=384 per joint, z=joints ----
    tgemm<<<dim3(3, NTOK/128, JJ), 256, TG_SMEM>>>(
        src_h, DDIM, 128, wqkv_t, EE, 384*128,
        qkv, 9216, 384, nullptr, nullptr, nullptr, 0, EE, 0, 0);

    // ---- temporal attention -> concat fp16 ----
    temporal_attn<<<dim3(JJ, HH, BB), 128>>>(qkv, cat_h);

    // ---- temporal projection + bias + residual ----
    tgemm<<<dim3(DDIM/128, NTOK/128, 1), 256, TG_SMEM>>>(
        cat_h, DDIM, 0, wpt_h, DDIM, 0,
        res1, DDIM, 0, nullptr, bp_t, src, DDIM, DDIM, 0, 0);

    // ---- spatial Q (per joint) and shared K/V ----
    tgemm<<<dim3(1, NTOK/128, JJ), 256, TG_SMEM>>>(
        src_h, DDIM, 128, wq_s, EE, 16384,
        qb, DDIM, 128, nullptr, nullptr, nullptr, 0, EE, 0, 0);
    tgemm<<<dim3(2, (NTOK*JJ)/128, 1), 256, TG_SMEM>>>(
        src_h, EE, 0, wkv_s, EE, 0,
        kvb, 256, 0, nullptr, nullptr, nullptr, 0, EE, 0, 0);

    // ---- spatial attention -> concat fp16 ----
    spatial_attn<<<NTOK, 256>>>(qb, kvb, cat_h);

    // ---- spatial projection + bias + residual ----
    tgemm<<<dim3(DDIM/128, NTOK/128, 1), 256, TG_SMEM>>>(
        cat_h, DDIM, 0, wps_h, DDIM, 0,
        res2, DDIM, 0, nullptr, bp_s, src, DDIM, DDIM, 0, 0);

    // ---- BN stats ----
    bn_stats1<<<dim3(DDIM/256, NROWCH), 256>>>(res1, ps, ps2);
    bn_stats2<<<DDIM/256, 256>>>(ps, ps2, mean, var);
    bn_stats1<<<dim3(DDIM/256, NROWCH), 256>>>(res2, ps, ps2);
    bn_stats2<<<DDIM/256, 256>>>(ps, ps2, mean + DDIM, var + DDIM);

    // ---- att = bn_t + bn_s ----
    combine_att<<<(NEL/4 + 255)/256, 256>>>(res1, res2, g_t, b_t, g_s, b_s,
                                            mean, var, att, att_h);

    // ---- FFN ----
    tgemm<<<dim3(FFD/128, NTOK/128, 1), 256, TG_SMEM>>>(
        att_h, DDIM, 0, w1_h, DDIM, 0,
        nullptr, FFD, 0, h1_h, b1, nullptr, 0, DDIM, 1, 1);
    tgemm<<<dim3(DDIM/128, NTOK/128, 1), 256, TG_SMEM>>>(
        h1_h, FFD, 0, w2_h, FFD, 0,
        qb, DDIM, 0, nullptr, b2, att, DDIM, FFD, 0, 0);

    // ---- final BN ----
    bn_stats1<<<dim3(DDIM/256, NROWCH), 256>>>(qb, ps, ps2);
    bn_stats2<<<DDIM/256, 256>>>(ps, ps2, mean + 2*DDIM, var + 2*DDIM);
    final_bn<<<(NEL/4 + 255)/256, 256>>>(qb, g_f, b_f, mean + 2*DDIM, var + 2*DDIM, out);
}